// round 16
// baseline (speedup 1.0000x reference)
#include <cuda_runtime.h>
#include <cuda_fp16.h>
#include <cstdint>

// Problem constants: B=4, N=1024, C=16, H=W=128
#define BB 4
#define NN 1024
#define CC 16
#define HW 128

#define EU_STRIDE 72                        // halfwords per padded eu row
#define FT_STRIDE 1032                      // halfwords per padded ft row
#define SEU_OFF   0u                        // 2 x 128 x 72 x 2B = 36864 (also epilogue sred)
#define SFT_OFF   36864u                    // 16 x 1032 x 2B   = 33024
#define SEV_OFF   69888u                    // 4 x 1024 x 2B    =  8192
#define SU_OFF    78080u                    // 1024 f32
#define SV_OFF    82176u
#define SSV_OFF   86272u
#define SIDX_OFF  90368u
#define SMEM_DYN  94464u

__device__ __forceinline__ float ex2f(float x) {
    float y;
    asm("ex2.approx.ftz.f32 %0, %1;" : "=f"(y) : "f"(x));
    return y;
}

__device__ __forceinline__ uint32_t smem_u32(const void* p) {
    uint32_t a;
    asm("{ .reg .u64 t; cvta.to.shared.u64 t, %1; cvt.u32.u64 %0, t; }"
        : "=r"(a) : "l"(p));
    return a;
}

__device__ __forceinline__ uint32_t hmul2(uint32_t a, uint32_t b) {
    uint32_t d;
    asm("mul.rn.f16x2 %0, %1, %2;" : "=r"(d) : "r"(a), "r"(b));
    return d;
}

__device__ __forceinline__ void ldsm_x4(uint32_t* r, uint32_t addr) {
    asm volatile("ldmatrix.sync.aligned.m8n8.x4.shared.b16 {%0,%1,%2,%3}, [%4];"
                 : "=r"(r[0]), "=r"(r[1]), "=r"(r[2]), "=r"(r[3]) : "r"(addr));
}

__device__ __forceinline__ void mma16816(float* d, const uint32_t* a,
                                         const uint32_t* b) {
    asm volatile(
        "mma.sync.aligned.m16n8k16.row.col.f32.f16.f16.f32 "
        "{%0,%1,%2,%3}, {%4,%5,%6,%7}, {%8,%9}, {%0,%1,%2,%3};"
        : "+f"(d[0]), "+f"(d[1]), "+f"(d[2]), "+f"(d[3])
        : "r"(a[0]), "r"(a[1]), "r"(a[2]), "r"(a[3]), "r"(b[0]), "r"(b[1]));
}

// Compute one 64-slot euT chunk (f16) into the smem double buffer.
// Thread covers gu row srow = t>>2, slots [k*64 + sq, +16).
__device__ __forceinline__ void compute_eu_chunk(
    char* smem, const float* su, const float* ssv,
    int k, int cnt, int srow, int sq)
{
    const int s0 = k * 64 + sq;
    const float fgu = (float)srow;
    float uu[16], ss[16];
    #pragma unroll
    for (int i = 0; i < 4; i++) {
        *(float4*)&uu[4 * i] = *(const float4*)&su[s0 + 4 * i];
        *(float4*)&ss[4 * i] = *(const float4*)&ssv[s0 + 4 * i];
    }
    uint32_t q[8];
    #pragma unroll
    for (int j = 0; j < 8; j++) {
        float h0 = 0.0f, h1 = 0.0f;
        if (s0 + 2 * j < cnt) {
            float d = uu[2 * j] - fgu;
            h0 = ex2f(d * d * ss[2 * j]);
        }
        if (s0 + 2 * j + 1 < cnt) {
            float d = uu[2 * j + 1] - fgu;
            h1 = ex2f(d * d * ss[2 * j + 1]);
        }
        asm("cvt.rn.f16x2.f32 %0, %1, %2;" : "=r"(q[j]) : "f"(h1), "f"(h0));
    }
    unsigned short* dst = (unsigned short*)(smem + SEU_OFF)
        + (k & 1) * (128 * EU_STRIDE) + srow * EU_STRIDE + sq;
    *(uint4*)dst       = make_uint4(q[0], q[1], q[2], q[3]);
    *(uint4*)(dst + 8) = make_uint4(q[4], q[5], q[6], q[7]);
}

// ---------------------------------------------------------------------------
// SINGLE fused kernel: projection + compaction + factors + HMMA GEMM.
// grid = B*32 = 128 CTAs = (b, 4 gv rows), 512 threads, one wave, no gmem
// scratch. R16: single-sync compaction, gather-before-sev overlap, and a
// coalesced epilogue via smem transpose (sred[64][132], conflict-free).
// ---------------------------------------------------------------------------
__global__ void __launch_bounds__(512, 1) fused_kernel(
    const float* __restrict__ Kc,
    const float* __restrict__ RT,
    const float* __restrict__ pts3d,
    const float* __restrict__ feat,
    const float* __restrict__ scale,
    float* __restrict__ out)
{
    extern __shared__ __align__(16) char smem[];
    unsigned short* sft = (unsigned short*)(smem + SFT_OFF);
    unsigned short* sev = (unsigned short*)(smem + SEV_OFF);
    float* su  = (float*)(smem + SU_OFF);
    float* sv  = (float*)(smem + SV_OFF);
    float* ssv = (float*)(smem + SSV_OFF);
    int*   sidx = (int*)(smem + SIDX_OFF);
    __shared__ int wcnt[32];

    const int b   = blockIdx.x >> 5;
    const int gv0 = (blockIdx.x & 31) << 2;
    const int t    = threadIdx.x;
    const int wid  = t >> 5;
    const int lane = t & 31;

    // camera params (broadcast loads)
    const float k0 = Kc[0], k1 = Kc[1], k2 = Kc[2];
    const float k3 = Kc[3], k4 = Kc[4], k5 = Kc[5];
    const float k6 = Kc[6], k7 = Kc[7], k8 = Kc[8];
    const float* rt = RT + b * 12;
    const float r0 = rt[0], r1 = rt[1], r2 = rt[2],  r3  = rt[3];
    const float r4 = rt[4], r5 = rt[5], r6 = rt[6],  r7  = rt[7];
    const float r8 = rt[8], r9 = rt[9], r10 = rt[10], r11 = rt[11];
    const float sig = k0 * 0.03125f;                  // sigma = K[0,0]/32

    // ---- project 2 points/thread; both ballots share ONE sync ----
    float u_[2], v_[2], si_[2];
    unsigned bal_[2];
    bool keep_[2];
    #pragma unroll
    for (int i = 0; i < 2; i++) {
        const int n = i * 512 + t;
        const float* p = pts3d + ((size_t)b * NN + n) * 3;
        const float p0 = p[0], p1 = p[1], p2 = p[2];
        const float scv = scale[b * NN + n];

        float l0 = r0 * p0 + r1 * p1 + r2  * p2 + r3;
        float l1 = r4 * p0 + r5 * p1 + r6  * p2 + r7;
        float l2 = r8 * p0 + r9 * p1 + r10 * p2 + r11;
        float x = k0 * l0 + k1 * l1 + k2 * l2;
        float y = k3 * l0 + k4 * l1 + k5 * l2;
        float z = k6 * l0 + k7 * l1 + k8 * l2;
        float zc = fmaxf(z, 0.1f);
        float u = x / zc, v = y / zc;
        float s = scv * sig * sig;
        float tt = sqrtf(17.5f * s);                  // f16-exact-zero radius
        keep_[i] = (z > 0.1f) && (u > -tt) && (u < 127.0f + tt)
                              && (v > -tt) && (v < 127.0f + tt);
        u_[i] = u; v_[i] = v; si_[i] = -1.4426950408889634f / s;
        bal_[i] = __ballot_sync(0xffffffffu, keep_[i]);
        if (lane == 0) wcnt[i * 16 + wid] = __popc(bal_[i]);
    }
    __syncthreads();

    int tot0 = 0, off0 = 0, off1 = 0, cnt = 0;
    #pragma unroll
    for (int w = 0; w < 16; w++) {
        const int c0_ = wcnt[w], c1_ = wcnt[16 + w];
        tot0 += c0_;
        cnt  += c0_ + c1_;
        if (w < wid) { off0 += c0_; off1 += c1_; }
    }
    off1 += tot0;
    #pragma unroll
    for (int i = 0; i < 2; i++) {
        if (keep_[i]) {
            const int slot = (i ? off1 : off0)
                           + __popc(bal_[i] & ((1u << lane) - 1));
            su[slot]  = u_[i];
            sv[slot]  = v_[i];
            ssv[slot] = si_[i];
            sidx[slot] = i * 512 + t;
        }
    }
    __syncthreads();

    const int pad = (cnt + 63) & ~63;
    const int nch = pad >> 6;

    // ---- sft FIRST: feat gather LDGs issue early, latency hides under sev ----
    {
        const int c = t & 15;
        for (int s = t >> 4; s < pad; s += 32) {
            float v = 0.0f;
            if (s < cnt)
                v = feat[((size_t)b * NN + sidx[s]) * CC + c];
            sft[c * FT_STRIDE + s] = __half_as_ushort(__float2half(v));
        }
    }
    // ---- sev: 4 ev rows over compact slots (zeros in pad) ----
    #pragma unroll
    for (int r = 0; r < 4; r++) {
        const float fg = (float)(gv0 + r);
        for (int s = t; s < pad; s += 512) {
            float hv = 0.0f;
            if (s < cnt) {
                float d = sv[s] - fg;
                hv = ex2f(d * d * ssv[s]);
            }
            sev[r * 1024 + s] = __half_as_ushort(__float2half(hv));
        }
    }

    // consumer / eu-compute mapping
    const int mt = wid & 7;
    const int rp = wid >> 3;
    const int c0 = (lane & 3) * 2;
    const int srow = t >> 2;
    const int sq   = (t & 3) * 16;

    const unsigned short* evr0 = sev + (rp * 2) * 1024;
    const unsigned short* evr1 = evr0 + 1024;

    const uint32_t sbase = smem_u32(smem);
    const uint32_t euLm0 = sbase + SEU_OFF +
        (uint32_t)(((mt * 16 + (lane & 15)) * EU_STRIDE + (lane >> 4) * 8) * 2);
    const uint32_t ftLm0 = sbase + SFT_OFF +
        (uint32_t)((((lane & 15)) * FT_STRIDE + (lane >> 4) * 8) * 2);

    float acc[2][2][4];
    #pragma unroll
    for (int rr = 0; rr < 2; rr++)
        #pragma unroll
        for (int nt = 0; nt < 2; nt++)
            #pragma unroll
            for (int q = 0; q < 4; q++) acc[rr][nt][q] = 0.0f;

    if (nch > 0) compute_eu_chunk(smem, su, ssv, 0, cnt, srow, sq);
    __syncthreads();

    #pragma unroll 1
    for (int k = 0; k < nch; k++) {
        if (k + 1 < nch)
            compute_eu_chunk(smem, su, ssv, k + 1, cnt, srow, sq);

        const int nb = k * 64;
        const uint32_t euLm = euLm0 + (uint32_t)(k & 1) * (128 * EU_STRIDE * 2);
        const uint32_t ftLm = ftLm0 + (uint32_t)(nb * 2);

        #pragma unroll
        for (int ks = 0; ks < 4; ks++) {
            const int nA = nb + ks * 16 + c0;
            const int nB = nA + 8;

            const uint32_t e0A = *(const uint32_t*)(evr0 + nA);
            const uint32_t e0B = *(const uint32_t*)(evr0 + nB);
            const uint32_t e1A = *(const uint32_t*)(evr1 + nA);
            const uint32_t e1B = *(const uint32_t*)(evr1 + nB);

            uint32_t u[4];
            ldsm_x4(u, euLm + (uint32_t)(ks * 32));

            uint32_t f[4];
            ldsm_x4(f, ftLm + (uint32_t)(ks * 32));
            uint32_t bf0[2] = { f[0], f[2] };
            uint32_t bf1[2] = { f[1], f[3] };

            uint32_t a0[4] = { hmul2(e0A, u[0]), hmul2(e0A, u[1]),
                               hmul2(e0B, u[2]), hmul2(e0B, u[3]) };
            mma16816(acc[0][0], a0, bf0);
            mma16816(acc[0][1], a0, bf1);

            uint32_t a1[4] = { hmul2(e1A, u[0]), hmul2(e1A, u[1]),
                               hmul2(e1B, u[2]), hmul2(e1B, u[3]) };
            mma16816(acc[1][0], a1, bf0);
            mma16816(acc[1][1], a1, bf1);
        }
        __syncthreads();
    }

    // ---- epilogue: smem transpose -> fully coalesced STG ----
    // sred[row=gvl*16+c][132 pad]; bank(word) = (4c+gu) mod 32: conflict-free.
    {
        float* sred = (float*)(smem + SEU_OFF);   // 64*132*4 = 33792 <= 36864
        const int guw = mt * 16 + (lane >> 2);
        const int c0w = (lane & 3) * 2;
        #pragma unroll
        for (int rr = 0; rr < 2; rr++) {
            const int gvl = rp * 2 + rr;
            #pragma unroll
            for (int nt = 0; nt < 2; nt++) {
                const int c = nt * 8 + c0w;
                sred[(gvl * 16 + c    ) * 132 + guw    ] = acc[rr][nt][0];
                sred[(gvl * 16 + c + 1) * 132 + guw    ] = acc[rr][nt][1];
                sred[(gvl * 16 + c    ) * 132 + guw + 8] = acc[rr][nt][2];
                sred[(gvl * 16 + c + 1) * 132 + guw + 8] = acc[rr][nt][3];
            }
        }
        __syncthreads();
        const int row = t >> 3;          // 0..63 = gvl*16 + c
        const int oct = t & 7;
        const int c   = row & 15;
        const int gvl = row >> 4;
        const float* srow = sred + row * 132 + oct * 16;
        float* ob = out + (size_t)b * CC * HW * HW + (size_t)c * HW * HW
                  + (size_t)(gv0 + gvl) * HW + oct * 16;
        #pragma unroll
        for (int i = 0; i < 4; i++)
            *(float4*)(ob + 4 * i) = *(const float4*)(srow + 4 * i);
    }
}

extern "C" void kernel_launch(void* const* d_in, const int* in_sizes, int n_in,
                              void* d_out, int out_size)
{
    const float* Kc    = (const float*)d_in[0];
    const float* RT    = (const float*)d_in[1];
    const float* pts3d = (const float*)d_in[2];
    const float* feat  = (const float*)d_in[3];
    const float* scale = (const float*)d_in[4];
    float* out = (float*)d_out;

    cudaFuncSetAttribute(fused_kernel,
                         cudaFuncAttributeMaxDynamicSharedMemorySize, SMEM_DYN);

    fused_kernel<<<BB * 32, 512, SMEM_DYN>>>(Kc, RT, pts3d, feat, scale, out);
}

// round 17
// speedup vs baseline: 1.1964x; 1.1964x over previous
#include <cuda_runtime.h>
#include <cuda_fp16.h>
#include <cstdint>

// Problem constants: B=4, N=1024, C=16, H=W=128
#define BB 4
#define NN 1024
#define CC 16
#define HW 128

// CTA tile: 16 gv rows x 32 gu cols (grid = 4b x 8 x 4 = 128)
#define EU_STRIDE 72                        // halfwords per padded eu row
#define FT_STRIDE 1032                      // halfwords per padded ft row
#define SEU_OFF   0u                        // 2 x 32 x 72 x 2B =  9216
#define SFT_OFF   9216u                     // 16 x 1032 x 2B   = 33024
#define SEV_OFF   42240u                    // 16 x 1024 x 2B   = 32768
#define SU_OFF    75008u                    // 1024 f32
#define SV_OFF    79104u
#define SSV_OFF   83200u
#define SIDX_OFF  87296u
#define SMEM_DYN  91392u

__device__ __forceinline__ float ex2f(float x) {
    float y;
    asm("ex2.approx.ftz.f32 %0, %1;" : "=f"(y) : "f"(x));
    return y;
}
__device__ __forceinline__ float rcpf(float x) {
    float y;
    asm("rcp.approx.ftz.f32 %0, %1;" : "=f"(y) : "f"(x));
    return y;
}
__device__ __forceinline__ float sqrtaf(float x) {
    float y;
    asm("sqrt.approx.ftz.f32 %0, %1;" : "=f"(y) : "f"(x));
    return y;
}

__device__ __forceinline__ uint32_t smem_u32(const void* p) {
    uint32_t a;
    asm("{ .reg .u64 t; cvta.to.shared.u64 t, %1; cvt.u32.u64 %0, t; }"
        : "=r"(a) : "l"(p));
    return a;
}

__device__ __forceinline__ uint32_t hmul2(uint32_t a, uint32_t b) {
    uint32_t d;
    asm("mul.rn.f16x2 %0, %1, %2;" : "=r"(d) : "r"(a), "r"(b));
    return d;
}

__device__ __forceinline__ void ldsm_x4(uint32_t* r, uint32_t addr) {
    asm volatile("ldmatrix.sync.aligned.m8n8.x4.shared.b16 {%0,%1,%2,%3}, [%4];"
                 : "=r"(r[0]), "=r"(r[1]), "=r"(r[2]), "=r"(r[3]) : "r"(addr));
}

__device__ __forceinline__ void mma16816(float* d, const uint32_t* a,
                                         const uint32_t* b) {
    asm volatile(
        "mma.sync.aligned.m16n8k16.row.col.f32.f16.f16.f32 "
        "{%0,%1,%2,%3}, {%4,%5,%6,%7}, {%8,%9}, {%0,%1,%2,%3};"
        : "+f"(d[0]), "+f"(d[1]), "+f"(d[2]), "+f"(d[3])
        : "r"(a[0]), "r"(a[1]), "r"(a[2]), "r"(a[3]), "r"(b[0]), "r"(b[1]));
}

// Compute one 64-slot euT chunk (f16, 32 LOCAL gu rows) into smem double buf.
// Thread covers local row srow = t>>4, slots [k*64 + sq, +4).
__device__ __forceinline__ void compute_eu_chunk(
    char* smem, const float* su, const float* ssv,
    int k, int cnt, int gu0, int srow, int sq)
{
    const int s0 = k * 64 + sq;
    const float fgu = (float)(gu0 + srow);
    float4 uu = *(const float4*)&su[s0];
    float4 ss = *(const float4*)&ssv[s0];
    float h0 = 0.f, h1 = 0.f, h2 = 0.f, h3 = 0.f;
    if (s0     < cnt) { float d = uu.x - fgu; h0 = ex2f(d * d * ss.x); }
    if (s0 + 1 < cnt) { float d = uu.y - fgu; h1 = ex2f(d * d * ss.y); }
    if (s0 + 2 < cnt) { float d = uu.z - fgu; h2 = ex2f(d * d * ss.z); }
    if (s0 + 3 < cnt) { float d = uu.w - fgu; h3 = ex2f(d * d * ss.w); }
    uint32_t q0, q1;
    asm("cvt.rn.f16x2.f32 %0, %1, %2;" : "=r"(q0) : "f"(h1), "f"(h0));
    asm("cvt.rn.f16x2.f32 %0, %1, %2;" : "=r"(q1) : "f"(h3), "f"(h2));
    unsigned short* dst = (unsigned short*)(smem + SEU_OFF)
        + (k & 1) * (32 * EU_STRIDE) + srow * EU_STRIDE + sq;
    *(uint2*)dst = make_uint2(q0, q1);
}

// ---------------------------------------------------------------------------
// SINGLE fused kernel, re-tiled: CTA = (b, 16 gv, 32 gu). Per-CTA factor
// work drops 2.75x (48*pad vs 132*pad ex2); projection uses MUFU approx
// rcp/sqrt. Same deterministic compaction, same HMMA inner loop.
// ---------------------------------------------------------------------------
__global__ void __launch_bounds__(512, 1) fused_kernel(
    const float* __restrict__ Kc,
    const float* __restrict__ RT,
    const float* __restrict__ pts3d,
    const float* __restrict__ feat,
    const float* __restrict__ scale,
    float* __restrict__ out)
{
    extern __shared__ __align__(16) char smem[];
    unsigned short* sft = (unsigned short*)(smem + SFT_OFF);
    unsigned short* sev = (unsigned short*)(smem + SEV_OFF);
    float* su  = (float*)(smem + SU_OFF);
    float* sv  = (float*)(smem + SV_OFF);
    float* ssv = (float*)(smem + SSV_OFF);
    int*   sidx = (int*)(smem + SIDX_OFF);
    __shared__ int wcnt[32];

    const int b   = blockIdx.x >> 5;
    const int rem = blockIdx.x & 31;
    const int gv0 = (rem >> 2) << 4;        // 8 gv-tiles of 16
    const int gu0 = (rem & 3) << 5;         // 4 gu-tiles of 32
    const int t    = threadIdx.x;
    const int wid  = t >> 5;
    const int lane = t & 31;

    // camera params (broadcast loads)
    const float k0 = Kc[0], k1 = Kc[1], k2 = Kc[2];
    const float k3 = Kc[3], k4 = Kc[4], k5 = Kc[5];
    const float k6 = Kc[6], k7 = Kc[7], k8 = Kc[8];
    const float* rt = RT + b * 12;
    const float r0 = rt[0], r1 = rt[1], r2 = rt[2],  r3  = rt[3];
    const float r4 = rt[4], r5 = rt[5], r6 = rt[6],  r7  = rt[7];
    const float r8 = rt[8], r9 = rt[9], r10 = rt[10], r11 = rt[11];
    const float sig = k0 * 0.03125f;                  // sigma = K[0,0]/32

    // ---- project 2 points/thread; both ballots share ONE sync ----
    float u_[2], v_[2], si_[2];
    unsigned bal_[2];
    bool keep_[2];
    #pragma unroll
    for (int i = 0; i < 2; i++) {
        const int n = i * 512 + t;
        const float* p = pts3d + ((size_t)b * NN + n) * 3;
        const float p0 = p[0], p1 = p[1], p2 = p[2];
        const float scv = scale[b * NN + n];

        float l0 = r0 * p0 + r1 * p1 + r2  * p2 + r3;
        float l1 = r4 * p0 + r5 * p1 + r6  * p2 + r7;
        float l2 = r8 * p0 + r9 * p1 + r10 * p2 + r11;
        float x = k0 * l0 + k1 * l1 + k2 * l2;
        float y = k3 * l0 + k4 * l1 + k5 * l2;
        float z = k6 * l0 + k7 * l1 + k8 * l2;
        float zc = fmaxf(z, 0.1f);
        float iz = rcpf(zc);
        float u = x * iz, v = y * iz;
        float s = scv * sig * sig;
        float tt = sqrtaf(17.5f * s);                 // f16-exact-zero radius
        keep_[i] = (z > 0.1f) && (u > -tt) && (u < 127.0f + tt)
                              && (v > -tt) && (v < 127.0f + tt);
        u_[i] = u; v_[i] = v;
        si_[i] = -1.4426950408889634f * rcpf(s);      // -log2(e)/s
        bal_[i] = __ballot_sync(0xffffffffu, keep_[i]);
        if (lane == 0) wcnt[i * 16 + wid] = __popc(bal_[i]);
    }
    __syncthreads();

    int tot0 = 0, off0 = 0, off1 = 0, cnt = 0;
    #pragma unroll
    for (int w = 0; w < 16; w++) {
        const int c0_ = wcnt[w], c1_ = wcnt[16 + w];
        tot0 += c0_;
        cnt  += c0_ + c1_;
        if (w < wid) { off0 += c0_; off1 += c1_; }
    }
    off1 += tot0;
    #pragma unroll
    for (int i = 0; i < 2; i++) {
        if (keep_[i]) {
            const int slot = (i ? off1 : off0)
                           + __popc(bal_[i] & ((1u << lane) - 1));
            su[slot]  = u_[i];
            sv[slot]  = v_[i];
            ssv[slot] = si_[i];
            sidx[slot] = i * 512 + t;
        }
    }
    __syncthreads();

    const int pad = (cnt + 63) & ~63;
    const int nch = pad >> 6;

    // ---- sft FIRST: feat gather LDGs issue early (latency hides under sev) ----
    {
        const int c = t & 15;
        for (int s = t >> 4; s < pad; s += 32) {
            float v = 0.0f;
            if (s < cnt)
                v = feat[((size_t)b * NN + sidx[s]) * CC + c];
            sft[c * FT_STRIDE + s] = __half_as_ushort(__float2half(v));
        }
    }
    // ---- sev: warp w computes ev row (gv0 + w) over compact slots ----
    {
        const float fg = (float)(gv0 + wid);
        for (int s = lane; s < pad; s += 32) {
            float hv = 0.0f;
            if (s < cnt) {
                float d = sv[s] - fg;
                hv = ex2f(d * d * ssv[s]);
            }
            sev[wid * 1024 + s] = __half_as_ushort(__float2half(hv));
        }
    }

    // consumer / eu-compute mapping
    const int mt = wid & 1;                 // gu tile of 16 within 32
    const int rp = wid >> 1;                // gv pair 0..7
    const int c0 = (lane & 3) * 2;
    const int srow = t >> 4;                // 0..31 local gu row
    const int sq   = (t & 15) * 4;          // 4 slots

    const unsigned short* evr0 = sev + (rp * 2) * 1024;
    const unsigned short* evr1 = evr0 + 1024;

    const uint32_t sbase = smem_u32(smem);
    const uint32_t euLm0 = sbase + SEU_OFF +
        (uint32_t)(((mt * 16 + (lane & 15)) * EU_STRIDE + (lane >> 4) * 8) * 2);
    const uint32_t ftLm0 = sbase + SFT_OFF +
        (uint32_t)((((lane & 15)) * FT_STRIDE + (lane >> 4) * 8) * 2);

    float acc[2][2][4];
    #pragma unroll
    for (int rr = 0; rr < 2; rr++)
        #pragma unroll
        for (int nt = 0; nt < 2; nt++)
            #pragma unroll
            for (int q = 0; q < 4; q++) acc[rr][nt][q] = 0.0f;

    if (nch > 0) compute_eu_chunk(smem, su, ssv, 0, cnt, gu0, srow, sq);
    __syncthreads();

    #pragma unroll 1
    for (int k = 0; k < nch; k++) {
        if (k + 1 < nch)
            compute_eu_chunk(smem, su, ssv, k + 1, cnt, gu0, srow, sq);

        const int nb = k * 64;
        const uint32_t euLm = euLm0 + (uint32_t)(k & 1) * (32 * EU_STRIDE * 2);
        const uint32_t ftLm = ftLm0 + (uint32_t)(nb * 2);

        #pragma unroll
        for (int ks = 0; ks < 4; ks++) {
            const int nA = nb + ks * 16 + c0;
            const int nB = nA + 8;

            const uint32_t e0A = *(const uint32_t*)(evr0 + nA);
            const uint32_t e0B = *(const uint32_t*)(evr0 + nB);
            const uint32_t e1A = *(const uint32_t*)(evr1 + nA);
            const uint32_t e1B = *(const uint32_t*)(evr1 + nB);

            uint32_t u[4];
            ldsm_x4(u, euLm + (uint32_t)(ks * 32));

            uint32_t f[4];
            ldsm_x4(f, ftLm + (uint32_t)(ks * 32));
            uint32_t bf0[2] = { f[0], f[2] };
            uint32_t bf1[2] = { f[1], f[3] };

            uint32_t a0[4] = { hmul2(e0A, u[0]), hmul2(e0A, u[1]),
                               hmul2(e0B, u[2]), hmul2(e0B, u[3]) };
            mma16816(acc[0][0], a0, bf0);
            mma16816(acc[0][1], a0, bf1);

            uint32_t a1[4] = { hmul2(e1A, u[0]), hmul2(e1A, u[1]),
                               hmul2(e1B, u[2]), hmul2(e1B, u[3]) };
            mma16816(acc[1][0], a1, bf0);
            mma16816(acc[1][1], a1, bf1);
        }
        __syncthreads();
    }

    // ---- epilogue: D[gu][c] -> out[b][c][gv][gu] ----
    {
        const int guw = gu0 + mt * 16 + (lane >> 2);
        const int c0w = (lane & 3) * 2;
        #pragma unroll
        for (int rr = 0; rr < 2; rr++) {
            const int gv = gv0 + rp * 2 + rr;
            float* ob = out + (size_t)b * CC * HW * HW + (size_t)gv * HW;
            #pragma unroll
            for (int nt = 0; nt < 2; nt++) {
                const int c = nt * 8 + c0w;
                ob[(size_t)c * HW * HW + guw]           = acc[rr][nt][0];
                ob[(size_t)(c + 1) * HW * HW + guw]     = acc[rr][nt][1];
                ob[(size_t)c * HW * HW + guw + 8]       = acc[rr][nt][2];
                ob[(size_t)(c + 1) * HW * HW + guw + 8] = acc[rr][nt][3];
            }
        }
    }
}

extern "C" void kernel_launch(void* const* d_in, const int* in_sizes, int n_in,
                              void* d_out, int out_size)
{
    const float* Kc    = (const float*)d_in[0];
    const float* RT    = (const float*)d_in[1];
    const float* pts3d = (const float*)d_in[2];
    const float* feat  = (const float*)d_in[3];
    const float* scale = (const float*)d_in[4];
    float* out = (float*)d_out;

    cudaFuncSetAttribute(fused_kernel,
                         cudaFuncAttributeMaxDynamicSharedMemorySize, SMEM_DYN);

    fused_kernel<<<BB * 32, 512, SMEM_DYN>>>(Kc, RT, pts3d, feat, scale, out);
}